// round 1
// baseline (speedup 1.0000x reference)
#include <cuda_runtime.h>
#include <math.h>

// Problem constants
#define BB     4
#define SEQ    2048
#define DMODEL 768
#define NH     12
#define HDIM   64
#define M_TOT  (BB * SEQ)      // 8192
#define N_QKV  (3 * DMODEL)    // 2304

// Scratch (device globals; no runtime allocation allowed)
__device__ float g_Q[BB * NH * SEQ * HDIM];     // 25 MB
__device__ float g_K[BB * NH * SEQ * HDIM];
__device__ float g_V[BB * NH * SEQ * HDIM];
__device__ float g_Ctx[BB * SEQ * DMODEL];      // attention output, (B,N,D)

// ---------------------------------------------------------------------------
// GEMM: C = A(MxK) * W(KxNcols) + bvec
// MODE 0: A = x, scatter into g_Q/g_K/g_V  (Ncols = 2304, K = 768)
// MODE 1: A = g_Ctx, write Cout (+bias)    (Ncols = 768,  K = 768)
// Tiles: BM=128, BN=64, BK=8, 256 threads, 8x4 per-thread register tile.
// ---------------------------------------------------------------------------
template <int MODE>
__global__ void __launch_bounds__(256) gemm_kernel(
    const float* __restrict__ A,
    const float* __restrict__ W,
    const float* __restrict__ bvec,
    float* __restrict__ Cout,
    int Ncols, int Kdim)
{
    __shared__ float As[8][132];   // transposed: As[k][m], 132 stride keeps f4 align
    __shared__ float Bs[8][68];    // Bs[k][n]

    const int tid = threadIdx.x;
    const int tx = tid & 15;       // 0..15 -> 4 cols each
    const int ty = tid >> 4;       // 0..15 -> 8 rows each
    const int m0 = blockIdx.y * 128;
    const int n0 = blockIdx.x * 64;

    const float* Ap = (MODE == 1) ? g_Ctx : A;

    // load index mapping
    const int arow = tid >> 1;          // 0..127
    const int acol = (tid & 1) * 4;     // 0 or 4
    const int brow = tid >> 5;          // 0..7
    const int bcol = (tid & 31) * 2;    // 0..62

    const float* Aptr = Ap + (size_t)(m0 + arow) * Kdim + acol;
    const float* Wptr = W + (size_t)brow * Ncols + n0 + bcol;

    float acc[8][4];
#pragma unroll
    for (int i = 0; i < 8; i++)
#pragma unroll
        for (int j = 0; j < 4; j++) acc[i][j] = 0.0f;

    for (int k0 = 0; k0 < Kdim; k0 += 8) {
        float4 av = *(const float4*)(Aptr + k0);
        As[acol + 0][arow] = av.x;
        As[acol + 1][arow] = av.y;
        As[acol + 2][arow] = av.z;
        As[acol + 3][arow] = av.w;
        float2 bv = *(const float2*)(Wptr + (size_t)k0 * Ncols);
        Bs[brow][bcol]     = bv.x;
        Bs[brow][bcol + 1] = bv.y;
        __syncthreads();

#pragma unroll
        for (int kk = 0; kk < 8; kk++) {
            float4 alo = *(const float4*)&As[kk][ty * 8];
            float4 ahi = *(const float4*)&As[kk][ty * 8 + 4];
            float4 b4  = *(const float4*)&Bs[kk][tx * 4];
            float a[8] = {alo.x, alo.y, alo.z, alo.w, ahi.x, ahi.y, ahi.z, ahi.w};
            float b[4] = {b4.x, b4.y, b4.z, b4.w};
#pragma unroll
            for (int i = 0; i < 8; i++)
#pragma unroll
                for (int j = 0; j < 4; j++)
                    acc[i][j] = fmaf(a[i], b[j], acc[i][j]);
        }
        __syncthreads();
    }

    if (MODE == 0) {
        // n-tile (64 wide, 64-aligned) never crosses a 768 or 64 boundary:
        const int t = n0 / DMODEL;                 // 0=Q,1=K,2=V
        const int h = (n0 % DMODEL) / HDIM;
        float* dst = (t == 0) ? g_Q : ((t == 1) ? g_K : g_V);
#pragma unroll
        for (int i = 0; i < 8; i++) {
            const int m  = m0 + ty * 8 + i;
            const int b  = m / SEQ;
            const int ns = m % SEQ;
            float* drow = dst + (((size_t)b * NH + h) * SEQ + ns) * HDIM + tx * 4;
            float4 o;
            o.x = acc[i][0] + bvec[n0 + tx * 4 + 0];
            o.y = acc[i][1] + bvec[n0 + tx * 4 + 1];
            o.z = acc[i][2] + bvec[n0 + tx * 4 + 2];
            o.w = acc[i][3] + bvec[n0 + tx * 4 + 3];
            *(float4*)drow = o;
        }
    } else {
#pragma unroll
        for (int i = 0; i < 8; i++) {
            const int m = m0 + ty * 8 + i;
            float4 o;
            o.x = acc[i][0] + bvec[n0 + tx * 4 + 0];
            o.y = acc[i][1] + bvec[n0 + tx * 4 + 1];
            o.z = acc[i][2] + bvec[n0 + tx * 4 + 2];
            o.w = acc[i][3] + bvec[n0 + tx * 4 + 3];
            *(float4*)(Cout + (size_t)m * Ncols + n0 + tx * 4) = o;
        }
    }
}

// ---------------------------------------------------------------------------
// Flash-style attention with additive bias.
// Block = (b, h, 64-row q tile). 256 threads (16x16), 4x4 per-thread S/O tiles.
// SMEM (dynamic, stride 68 keeps float4 alignment):
//   Qs[d][r], Ks[d][c], Vs[c][d], Ps[c][r]
// ---------------------------------------------------------------------------
#define SM_STRIDE 68
#define ATTN_SMEM (4 * 64 * SM_STRIDE * 4)

__global__ void __launch_bounds__(256) attn_kernel(const float* __restrict__ bias)
{
    extern __shared__ float sm[];
    float (*Qs)[SM_STRIDE] = (float(*)[SM_STRIDE])(sm);
    float (*Ks)[SM_STRIDE] = (float(*)[SM_STRIDE])(sm + 1 * 64 * SM_STRIDE);
    float (*Vs)[SM_STRIDE] = (float(*)[SM_STRIDE])(sm + 2 * 64 * SM_STRIDE);
    float (*Ps)[SM_STRIDE] = (float(*)[SM_STRIDE])(sm + 3 * 64 * SM_STRIDE);

    const int tid = threadIdx.x;
    const int tx = tid & 15;
    const int ty = tid >> 4;
    const int q0 = blockIdx.x * 64;
    const int h  = blockIdx.y;
    const int b  = blockIdx.z;

    const float* Qg = g_Q + ((size_t)b * NH + h) * SEQ * HDIM;
    const float* Kg = g_K + ((size_t)b * NH + h) * SEQ * HDIM;
    const float* Vg = g_V + ((size_t)b * NH + h) * SEQ * HDIM;
    const float* biasg = bias + ((size_t)h * SEQ + q0) * SEQ;

    // Load Q tile transposed: Qs[d][r]
    {
        const int r  = tid >> 2;
        const int d0 = (tid & 3) * 16;
        const float* src = Qg + (size_t)(q0 + r) * HDIM + d0;
#pragma unroll
        for (int v = 0; v < 4; v++) {
            float4 x = *(const float4*)(src + v * 4);
            Qs[d0 + v * 4 + 0][r] = x.x;
            Qs[d0 + v * 4 + 1][r] = x.y;
            Qs[d0 + v * 4 + 2][r] = x.z;
            Qs[d0 + v * 4 + 3][r] = x.w;
        }
    }

    float o[4][4];
    float m_i[4], l_i[4];
#pragma unroll
    for (int i = 0; i < 4; i++) {
        m_i[i] = -INFINITY; l_i[i] = 0.0f;
#pragma unroll
        for (int j = 0; j < 4; j++) o[i][j] = 0.0f;
    }
    const float scale = 0.125f;  // 1/sqrt(64)

    for (int j0 = 0; j0 < SEQ; j0 += 64) {
        __syncthreads();  // prior iteration done reading Ks/Vs/Ps
        // Load K (transposed) and V tiles
        {
            const int r  = tid >> 2;
            const int d0 = (tid & 3) * 16;
            const float* ks = Kg + (size_t)(j0 + r) * HDIM + d0;
            const float* vs = Vg + (size_t)(j0 + r) * HDIM + d0;
#pragma unroll
            for (int v = 0; v < 4; v++) {
                float4 kx = *(const float4*)(ks + v * 4);
                Ks[d0 + v * 4 + 0][r] = kx.x;
                Ks[d0 + v * 4 + 1][r] = kx.y;
                Ks[d0 + v * 4 + 2][r] = kx.z;
                Ks[d0 + v * 4 + 3][r] = kx.w;
                float4 vx = *(const float4*)(vs + v * 4);
                *(float4*)&Vs[r][d0 + v * 4] = vx;
            }
        }
        __syncthreads();

        // S = Q K^T  (4x4 per thread)
        float s[4][4];
#pragma unroll
        for (int i = 0; i < 4; i++)
#pragma unroll
            for (int j = 0; j < 4; j++) s[i][j] = 0.0f;
#pragma unroll 8
        for (int d = 0; d < 64; d++) {
            float4 qa = *(const float4*)&Qs[d][ty * 4];
            float4 kb = *(const float4*)&Ks[d][tx * 4];
            float qv[4] = {qa.x, qa.y, qa.z, qa.w};
            float kv[4] = {kb.x, kb.y, kb.z, kb.w};
#pragma unroll
            for (int i = 0; i < 4; i++)
#pragma unroll
                for (int j = 0; j < 4; j++)
                    s[i][j] = fmaf(qv[i], kv[j], s[i][j]);
        }

        // scale + bias
#pragma unroll
        for (int i = 0; i < 4; i++) {
            float4 bz = *(const float4*)(biasg + (size_t)(ty * 4 + i) * SEQ + j0 + tx * 4);
            s[i][0] = fmaf(s[i][0], scale, bz.x);
            s[i][1] = fmaf(s[i][1], scale, bz.y);
            s[i][2] = fmaf(s[i][2], scale, bz.z);
            s[i][3] = fmaf(s[i][3], scale, bz.w);
        }

        // online softmax update (row reductions across the 16 tx lanes)
        float alpha[4];
#pragma unroll
        for (int i = 0; i < 4; i++) {
            float mx = fmaxf(fmaxf(s[i][0], s[i][1]), fmaxf(s[i][2], s[i][3]));
#pragma unroll
            for (int off = 8; off >= 1; off >>= 1)
                mx = fmaxf(mx, __shfl_xor_sync(0xffffffffu, mx, off));
            float mn = fmaxf(m_i[i], mx);
            alpha[i] = __expf(m_i[i] - mn);
            m_i[i] = mn;
            float rs = 0.0f;
#pragma unroll
            for (int j = 0; j < 4; j++) {
                s[i][j] = __expf(s[i][j] - mn);
                rs += s[i][j];
            }
#pragma unroll
            for (int off = 8; off >= 1; off >>= 1)
                rs += __shfl_xor_sync(0xffffffffu, rs, off);
            l_i[i] = l_i[i] * alpha[i] + rs;
        }

        // P -> SMEM transposed: Ps[c][r]
#pragma unroll
        for (int j = 0; j < 4; j++) {
            float4 pv = make_float4(s[0][j], s[1][j], s[2][j], s[3][j]);
            *(float4*)&Ps[tx * 4 + j][ty * 4] = pv;
        }

        // rescale running O
#pragma unroll
        for (int i = 0; i < 4; i++)
#pragma unroll
            for (int j = 0; j < 4; j++) o[i][j] *= alpha[i];

        __syncthreads();

        // O += P * V
#pragma unroll 8
        for (int c = 0; c < 64; c++) {
            float4 pa = *(const float4*)&Ps[c][ty * 4];
            float4 vb = *(const float4*)&Vs[c][tx * 4];
            float pv[4] = {pa.x, pa.y, pa.z, pa.w};
            float vv[4] = {vb.x, vb.y, vb.z, vb.w};
#pragma unroll
            for (int i = 0; i < 4; i++)
#pragma unroll
                for (int j = 0; j < 4; j++)
                    o[i][j] = fmaf(pv[i], vv[j], o[i][j]);
        }
    }

    // epilogue: normalize and write to (B,N,D) context buffer
    float* Cg = g_Ctx + ((size_t)b * SEQ + q0) * DMODEL + h * HDIM;
#pragma unroll
    for (int i = 0; i < 4; i++) {
        float inv = 1.0f / l_i[i];
        float4 ov = make_float4(o[i][0] * inv, o[i][1] * inv, o[i][2] * inv, o[i][3] * inv);
        *(float4*)(Cg + (size_t)(ty * 4 + i) * DMODEL + tx * 4) = ov;
    }
}

// ---------------------------------------------------------------------------
extern "C" void kernel_launch(void* const* d_in, const int* in_sizes, int n_in,
                              void* d_out, int out_size)
{
    const float* x     = (const float*)d_in[0];
    const float* bias  = (const float*)d_in[1];
    const float* Wqkv  = (const float*)d_in[2];
    const float* bqkv  = (const float*)d_in[3];
    const float* Wproj = (const float*)d_in[4];
    const float* bproj = (const float*)d_in[5];
    float* out = (float*)d_out;

    cudaFuncSetAttribute(attn_kernel,
                         cudaFuncAttributeMaxDynamicSharedMemorySize, ATTN_SMEM);

    // 1) QKV projection + scatter to (B,H,N,HD)
    {
        dim3 grid(N_QKV / 64, M_TOT / 128);
        gemm_kernel<0><<<grid, 256>>>(x, Wqkv, bqkv, nullptr, N_QKV, DMODEL);
    }
    // 2) attention
    {
        dim3 grid(SEQ / 64, NH, BB);
        attn_kernel<<<grid, 256, ATTN_SMEM>>>(bias);
    }
    // 3) output projection
    {
        dim3 grid(DMODEL / 64, M_TOT / 128);
        gemm_kernel<1><<<grid, 256>>>(nullptr, Wproj, bproj, out, DMODEL, DMODEL);
    }
}

// round 3
// speedup vs baseline: 1.1577x; 1.1577x over previous
#include <cuda_runtime.h>
#include <math.h>

// Problem constants
#define BB     4
#define SEQ    2048
#define DMODEL 768
#define NH     12
#define HDIM   64
#define M_TOT  (BB * SEQ)      // 8192
#define N_QKV  (3 * DMODEL)    // 2304

// Scratch (device globals; no runtime allocation allowed)
__device__ float g_Q[BB * NH * SEQ * HDIM];
__device__ float g_K[BB * NH * SEQ * HDIM];
__device__ float g_V[BB * NH * SEQ * HDIM];
__device__ float g_Ctx[BB * SEQ * DMODEL];

// ---------------------------------------------------------------------------
// tf32 helpers
// ---------------------------------------------------------------------------
__device__ __forceinline__ unsigned cvt_tf32(float x) {
    unsigned u;
    asm("cvt.rna.tf32.f32 %0, %1;" : "=r"(u) : "f"(x));
    return u;
}
__device__ __forceinline__ void split_tf32(float x, float& h, float& l) {
    h = __uint_as_float(cvt_tf32(x));
    l = __uint_as_float(cvt_tf32(x - h));
}
__device__ __forceinline__ void mma8(float* c, const unsigned* a, const unsigned* b) {
    asm volatile(
        "mma.sync.aligned.m16n8k8.row.col.f32.tf32.tf32.f32 "
        "{%0,%1,%2,%3},{%4,%5,%6,%7},{%8,%9},{%0,%1,%2,%3};\n"
        : "+f"(c[0]), "+f"(c[1]), "+f"(c[2]), "+f"(c[3])
        : "r"(a[0]), "r"(a[1]), "r"(a[2]), "r"(a[3]), "r"(b[0]), "r"(b[1]));
}
#define FU(x) __float_as_uint(x)

// ---------------------------------------------------------------------------
// GEMM (3xTF32): C = A(MxK) * W(KxN) + bvec
// MODE 0: A = x, scatter into g_Q/g_K/g_V   (N = 2304, K = 768)
// MODE 1: A = g_Ctx, write Cout (+bias)     (N = 768,  K = 768)
// Block 128x64, BK=16, 256 threads; warps 4(M)x2(N), warp tile 32x32.
// ---------------------------------------------------------------------------
template <int MODE>
__global__ void __launch_bounds__(256, 1) gemm_tc(
    const float* __restrict__ A,
    const float* __restrict__ W,
    const float* __restrict__ bvec,
    float* __restrict__ Cout,
    int Ncols, int Kdim)
{
    __shared__ float Ah[16 * 136], Al[16 * 136];
    __shared__ float Bh[16 * 72],  Bl[16 * 72];

    const int tid = threadIdx.x, lane = tid & 31, warp = tid >> 5;
    const int wm = (warp >> 1) * 32, wn = (warp & 1) * 32;
    const int g = lane >> 2, tig = lane & 3;
    const int m0 = blockIdx.y * 128, n0 = blockIdx.x * 64;

    const float* Ap = (MODE == 1) ? g_Ctx : A;

    const int am = tid >> 1, akb = (tid & 1) * 8;
    const int bk = tid >> 4, bn = (tid & 15) * 4;
    const float* Ag = Ap + (size_t)(m0 + am) * Kdim + akb;
    const float* Wg = W + (size_t)bk * Ncols + n0 + bn;

    float c[2][4][4];
#pragma unroll
    for (int mt = 0; mt < 2; mt++)
#pragma unroll
        for (int nt = 0; nt < 4; nt++)
#pragma unroll
            for (int i = 0; i < 4; i++) c[mt][nt][i] = 0.0f;

    float4 pa0 = *(const float4*)(Ag);
    float4 pa1 = *(const float4*)(Ag + 4);
    float4 pb  = *(const float4*)(Wg);

    for (int k0 = 0; k0 < Kdim; k0 += 16) {
        // split + store staged regs
        {
            float av[8] = {pa0.x, pa0.y, pa0.z, pa0.w, pa1.x, pa1.y, pa1.z, pa1.w};
#pragma unroll
            for (int i = 0; i < 8; i++) {
                float h, l; split_tf32(av[i], h, l);
                Ah[(akb + i) * 136 + am] = h;
                Al[(akb + i) * 136 + am] = l;
            }
            float bv[4] = {pb.x, pb.y, pb.z, pb.w};
#pragma unroll
            for (int i = 0; i < 4; i++) {
                float h, l; split_tf32(bv[i], h, l);
                Bh[bk * 72 + bn + i] = h;
                Bl[bk * 72 + bn + i] = l;
            }
        }
        __syncthreads();

        if (k0 + 16 < Kdim) {
            pa0 = *(const float4*)(Ag + k0 + 16);
            pa1 = *(const float4*)(Ag + k0 + 20);
            pb  = *(const float4*)(Wg + (size_t)(k0 + 16) * Ncols);
        }

#pragma unroll
        for (int ks = 0; ks < 2; ks++) {
            const int kb = ks * 8;
            unsigned ah[2][4], al[2][4];
#pragma unroll
            for (int mt = 0; mt < 2; mt++) {
                const int mb = wm + mt * 16 + g;
                ah[mt][0] = FU(Ah[(kb + tig) * 136 + mb]);
                ah[mt][1] = FU(Ah[(kb + tig) * 136 + mb + 8]);
                ah[mt][2] = FU(Ah[(kb + tig + 4) * 136 + mb]);
                ah[mt][3] = FU(Ah[(kb + tig + 4) * 136 + mb + 8]);
                al[mt][0] = FU(Al[(kb + tig) * 136 + mb]);
                al[mt][1] = FU(Al[(kb + tig) * 136 + mb + 8]);
                al[mt][2] = FU(Al[(kb + tig + 4) * 136 + mb]);
                al[mt][3] = FU(Al[(kb + tig + 4) * 136 + mb + 8]);
            }
#pragma unroll
            for (int nt = 0; nt < 4; nt++) {
                const int nb = wn + nt * 8 + g;
                unsigned bh[2], bl[2];
                bh[0] = FU(Bh[(kb + tig) * 72 + nb]);
                bh[1] = FU(Bh[(kb + tig + 4) * 72 + nb]);
                bl[0] = FU(Bl[(kb + tig) * 72 + nb]);
                bl[1] = FU(Bl[(kb + tig + 4) * 72 + nb]);
#pragma unroll
                for (int mt = 0; mt < 2; mt++) {
                    mma8(c[mt][nt], ah[mt], bh);
                    mma8(c[mt][nt], ah[mt], bl);
                    mma8(c[mt][nt], al[mt], bh);
                }
            }
        }
        __syncthreads();
    }

    // epilogue
    if (MODE == 0) {
        const int t = n0 / DMODEL;
        const int hh = (n0 % DMODEL) / HDIM;
        const int bidx = m0 / SEQ;
        const int ns0 = m0 % SEQ;
        float* dst = (t == 0) ? g_Q : ((t == 1) ? g_K : g_V);
        float* base = dst + ((size_t)bidx * NH + hh) * SEQ * HDIM;
#pragma unroll
        for (int mt = 0; mt < 2; mt++)
#pragma unroll
            for (int nt = 0; nt < 4; nt++) {
                const int hd = wn + nt * 8 + 2 * tig;
                const float b0 = bvec[n0 + hd], b1 = bvec[n0 + hd + 1];
                const int r = ns0 + wm + mt * 16 + g;
                *(float2*)(base + (size_t)r * HDIM + hd) =
                    make_float2(c[mt][nt][0] + b0, c[mt][nt][1] + b1);
                *(float2*)(base + (size_t)(r + 8) * HDIM + hd) =
                    make_float2(c[mt][nt][2] + b0, c[mt][nt][3] + b1);
            }
    } else {
#pragma unroll
        for (int mt = 0; mt < 2; mt++)
#pragma unroll
            for (int nt = 0; nt < 4; nt++) {
                const int ncol = n0 + wn + nt * 8 + 2 * tig;
                const float b0 = bvec[ncol], b1 = bvec[ncol + 1];
                const int r = m0 + wm + mt * 16 + g;
                *(float2*)(Cout + (size_t)r * Ncols + ncol) =
                    make_float2(c[mt][nt][0] + b0, c[mt][nt][1] + b1);
                *(float2*)(Cout + (size_t)(r + 8) * Ncols + ncol) =
                    make_float2(c[mt][nt][2] + b0, c[mt][nt][3] + b1);
            }
    }
}

// ---------------------------------------------------------------------------
// Flash attention, 3xTF32 mma. Block = 128 q rows, 8 warps (16 rows each),
// KV tiles of 64. SMEM: Kh/Kl/Vh/Vl [64][72], Ph/Pl [64][136].
// ---------------------------------------------------------------------------
#define AT_SMEM ((4 * 64 * 72 + 2 * 64 * 136) * 4)

__global__ void __launch_bounds__(256, 1) attn_tc(const float* __restrict__ bias)
{
    extern __shared__ float sm[];
    float* Kh = sm;
    float* Kl = Kh + 64 * 72;
    float* Vh = Kl + 64 * 72;
    float* Vl = Vh + 64 * 72;
    float* Ph = Vl + 64 * 72;
    float* Pl = Ph + 64 * 136;

    const int tid = threadIdx.x, lane = tid & 31, w = tid >> 5;
    const int g = lane >> 2, tig = lane & 3;
    const int q0 = blockIdx.x * 128, h = blockIdx.y, b = blockIdx.z;

    const float* Qg = g_Q + ((size_t)b * NH + h) * SEQ * HDIM;
    const float* Kg = g_K + ((size_t)b * NH + h) * SEQ * HDIM;
    const float* Vg = g_V + ((size_t)b * NH + h) * SEQ * HDIM;
    const float* biasg = bias + ((size_t)h * SEQ + q0 + 16 * w) * SEQ;

    // stage Q transposed [d][qrow] into Ph (stride 136)
    {
        const int qr = tid >> 1, db = (tid & 1) * 32;
        const float* src = Qg + (size_t)(q0 + qr) * HDIM + db;
#pragma unroll
        for (int u = 0; u < 8; u++) {
            float4 v = *(const float4*)(src + u * 4);
            Ph[(db + u * 4 + 0) * 136 + qr] = v.x;
            Ph[(db + u * 4 + 1) * 136 + qr] = v.y;
            Ph[(db + u * 4 + 2) * 136 + qr] = v.z;
            Ph[(db + u * 4 + 3) * 136 + qr] = v.w;
        }
    }
    __syncthreads();

    // Q fragments (hi/lo) held in registers
    unsigned qh[8][4], ql[8][4];
#pragma unroll
    for (int kt = 0; kt < 8; kt++) {
        const int kr = kt * 8 + tig;
        float f[4];
        f[0] = Ph[kr * 136 + 16 * w + g];
        f[1] = Ph[kr * 136 + 16 * w + g + 8];
        f[2] = Ph[(kr + 4) * 136 + 16 * w + g];
        f[3] = Ph[(kr + 4) * 136 + 16 * w + g + 8];
#pragma unroll
        for (int i = 0; i < 4; i++) {
            float hv, lv; split_tf32(f[i], hv, lv);
            qh[kt][i] = FU(hv); ql[kt][i] = FU(lv);
        }
    }
    __syncthreads();

    float o[8][4];
#pragma unroll
    for (int nt = 0; nt < 8; nt++)
#pragma unroll
        for (int i = 0; i < 4; i++) o[nt][i] = 0.0f;
    float mi[2] = {-1e30f, -1e30f}, li[2] = {0.0f, 0.0f};

    const int token = tid >> 2, dseg = (tid & 3) * 16;
    const float* Krow = Kg + (size_t)token * HDIM + dseg;
    const float* Vrow = Vg + (size_t)token * HDIM + dseg;

    for (int j0 = 0; j0 < SEQ; j0 += 64) {
        // S accumulators pre-initialized with 8*bias (scale folded later)
        float c[8][4];
#pragma unroll
        for (int nt = 0; nt < 8; nt++) {
            const float* bp = biasg + j0 + nt * 8 + 2 * tig;
            float2 b0 = *(const float2*)(bp + (size_t)g * SEQ);
            float2 b1 = *(const float2*)(bp + (size_t)(g + 8) * SEQ);
            c[nt][0] = b0.x * 8.0f; c[nt][1] = b0.y * 8.0f;
            c[nt][2] = b1.x * 8.0f; c[nt][3] = b1.y * 8.0f;
        }
        // load + split K/V tile
#pragma unroll
        for (int u = 0; u < 4; u++) {
            float4 kv = *(const float4*)(Krow + (size_t)j0 * HDIM + u * 4);
            float kf[4] = {kv.x, kv.y, kv.z, kv.w};
#pragma unroll
            for (int i = 0; i < 4; i++) {
                float hv, lv; split_tf32(kf[i], hv, lv);
                Kh[(dseg + u * 4 + i) * 72 + token] = hv;
                Kl[(dseg + u * 4 + i) * 72 + token] = lv;
            }
            float4 vv = *(const float4*)(Vrow + (size_t)j0 * HDIM + u * 4);
            float4 hv4, lv4;
            split_tf32(vv.x, hv4.x, lv4.x);
            split_tf32(vv.y, hv4.y, lv4.y);
            split_tf32(vv.z, hv4.z, lv4.z);
            split_tf32(vv.w, hv4.w, lv4.w);
            *(float4*)&Vh[token * 72 + dseg + u * 4] = hv4;
            *(float4*)&Vl[token * 72 + dseg + u * 4] = lv4;
        }
        __syncthreads();

        // S += Q K^T
#pragma unroll
        for (int kt = 0; kt < 8; kt++) {
            const int kr = kt * 8 + tig;
#pragma unroll
            for (int nt = 0; nt < 8; nt++) {
                const int nb = nt * 8 + g;
                unsigned bh[2], bl[2];
                bh[0] = FU(Kh[kr * 72 + nb]);
                bh[1] = FU(Kh[(kr + 4) * 72 + nb]);
                bl[0] = FU(Kl[kr * 72 + nb]);
                bl[1] = FU(Kl[(kr + 4) * 72 + nb]);
                mma8(c[nt], qh[kt], bh);
                mma8(c[nt], qh[kt], bl);
                mma8(c[nt], ql[kt], bh);
            }
        }

        // online softmax (rows g, g+8)
        float alpha[2];
#pragma unroll
        for (int r = 0; r < 2; r++) {
            const int e0 = r * 2;
            float mx = -1e30f;
#pragma unroll
            for (int nt = 0; nt < 8; nt++)
                mx = fmaxf(mx, fmaxf(c[nt][e0], c[nt][e0 + 1]));
            mx = fmaxf(mx, __shfl_xor_sync(0xffffffffu, mx, 1));
            mx = fmaxf(mx, __shfl_xor_sync(0xffffffffu, mx, 2));
            const float mn = fmaxf(mi[r], mx * 0.125f);
            alpha[r] = __expf(mi[r] - mn);
            mi[r] = mn;
            float rs = 0.0f;
#pragma unroll
            for (int nt = 0; nt < 8; nt++) {
                float p0 = __expf(fmaf(c[nt][e0], 0.125f, -mn));
                float p1 = __expf(fmaf(c[nt][e0 + 1], 0.125f, -mn));
                c[nt][e0] = p0; c[nt][e0 + 1] = p1;
                rs += p0 + p1;
            }
            rs += __shfl_xor_sync(0xffffffffu, rs, 1);
            rs += __shfl_xor_sync(0xffffffffu, rs, 2);
            li[r] = li[r] * alpha[r] + rs;
#pragma unroll
            for (int nt = 0; nt < 8; nt++) {
                o[nt][e0]     *= alpha[r];
                o[nt][e0 + 1] *= alpha[r];
            }
        }

        // store P (split) to SMEM [token][qrow]
#pragma unroll
        for (int nt = 0; nt < 8; nt++)
#pragma unroll
            for (int e = 0; e < 2; e++) {
                const int col = nt * 8 + 2 * tig + e;
                float hv, lv;
                split_tf32(c[nt][e], hv, lv);
                Ph[col * 136 + 16 * w + g] = hv;
                Pl[col * 136 + 16 * w + g] = lv;
                split_tf32(c[nt][2 + e], hv, lv);
                Ph[col * 136 + 16 * w + g + 8] = hv;
                Pl[col * 136 + 16 * w + g + 8] = lv;
            }
        __syncthreads();

        // O += P V
#pragma unroll
        for (int kt = 0; kt < 8; kt++) {
            const int kr = kt * 8 + tig;
            unsigned ph[4], pl[4];
            ph[0] = FU(Ph[kr * 136 + 16 * w + g]);
            ph[1] = FU(Ph[kr * 136 + 16 * w + g + 8]);
            ph[2] = FU(Ph[(kr + 4) * 136 + 16 * w + g]);
            ph[3] = FU(Ph[(kr + 4) * 136 + 16 * w + g + 8]);
            pl[0] = FU(Pl[kr * 136 + 16 * w + g]);
            pl[1] = FU(Pl[kr * 136 + 16 * w + g + 8]);
            pl[2] = FU(Pl[(kr + 4) * 136 + 16 * w + g]);
            pl[3] = FU(Pl[(kr + 4) * 136 + 16 * w + g + 8]);
#pragma unroll
            for (int nt = 0; nt < 8; nt++) {
                const int nb = nt * 8 + g;
                unsigned bh[2], bl[2];
                bh[0] = FU(Vh[kr * 72 + nb]);
                bh[1] = FU(Vh[(kr + 4) * 72 + nb]);
                bl[0] = FU(Vl[kr * 72 + nb]);
                bl[1] = FU(Vl[(kr + 4) * 72 + nb]);
                mma8(o[nt], ph, bh);
                mma8(o[nt], ph, bl);
                mma8(o[nt], pl, bh);
            }
        }
        __syncthreads();
    }

    // epilogue
    float* Cg = g_Ctx + ((size_t)b * SEQ + q0 + 16 * w) * DMODEL + h * HDIM;
#pragma unroll
    for (int r = 0; r < 2; r++) {
        const float inv = 1.0f / li[r];
        float* rp = Cg + (size_t)(g + 8 * r) * DMODEL;
#pragma unroll
        for (int nt = 0; nt < 8; nt++)
            *(float2*)(rp + nt * 8 + 2 * tig) =
                make_float2(o[nt][r * 2] * inv, o[nt][r * 2 + 1] * inv);
    }
}

// ---------------------------------------------------------------------------
extern "C" void kernel_launch(void* const* d_in, const int* in_sizes, int n_in,
                              void* d_out, int out_size)
{
    const float* x     = (const float*)d_in[0];
    const float* bias  = (const float*)d_in[1];
    const float* Wqkv  = (const float*)d_in[2];
    const float* bqkv  = (const float*)d_in[3];
    const float* Wproj = (const float*)d_in[4];
    const float* bproj = (const float*)d_in[5];
    float* out = (float*)d_out;

    cudaFuncSetAttribute(attn_tc,
                         cudaFuncAttributeMaxDynamicSharedMemorySize, AT_SMEM);

    {
        dim3 grid(N_QKV / 64, M_TOT / 128);
        gemm_tc<0><<<grid, 256>>>(x, Wqkv, bqkv, nullptr, N_QKV, DMODEL);
    }
    {
        dim3 grid(SEQ / 128, NH, BB);
        attn_tc<<<grid, 256, AT_SMEM>>>(bias);
    }
    {
        dim3 grid(DMODEL / 64, M_TOT / 128);
        gemm_tc<1><<<grid, 256>>>(nullptr, Wproj, bproj, out, DMODEL, DMODEL);
    }
}